// round 11
// baseline (speedup 1.0000x reference)
#include <cuda_runtime.h>

// HONU degree-3: out[r] = sum_{a<=b<=c} w(a,b,c) * xs[a][r]*xs[b][r]*xs[c][r]
// xs[0][r]=1 (bias). Weight index = lexicographic rank (closed form); the
// comb_idx input is redundant and ignored.
//
// Pair factorization: s_ab[r] = sum_c w_abc * xs[c][r];
//                     out[r] += xs[a][r]*xs[b][r]*s_ab[r].
// FOUR 'a'-streams share each xs[c] LDS.128. Each thread owns 4 rows (2x
// packed fma.rn.f32x2); a warp covers a 128-row half and warp PAIRS share a
// weight range (2nd warp's uniform LDGs hit L1). This keeps live state ~55-60
// regs -> 1024 threads/block under the 64-reg cap -> 8 warps/SMSP (2x R10's
// latency hiding; R10 was RF-limited at 126 regs x 512 thr = full RF).
// Grid=148 (1 wave). Cross-block reduction fused via atomic ticket.

#define NFEAT 129
#define NROW  256
#define NBLK  148
#define WPB   32
#define NRANGE (NBLK * WPB / 2)   // 2368 ranges (2 warps each: row halves)

__host__ __device__ __forceinline__ int c2i(int v) { return v * (v - 1) / 2; }
__host__ __device__ __forceinline__ int c3i(int v) { return v * (v - 1) * (v - 2) / 6; }

// flat lexicographic rank of combo (a, b, b); total combos = C(131,3) = 366145
__device__ __forceinline__ int comb_base(int a, int b) {
    return 366145 - c3i(131 - a) + c2i(130 - a) - c2i(130 - b);
}

// total c-steps over all (b, quartet) rows: sum_b (b/4+1)*(129-b)
constexpr int t4_calc() {
    int t = 0;
    for (int b = 0; b < NFEAT; b++) t += (b / 4 + 1) * (NFEAT - b);
    return t;
}
constexpr int T4 = t4_calc();

__device__ float g_partial[NBLK * NROW];
__device__ int   g_count = 0;

__device__ __forceinline__ unsigned long long pack2(float w) {
    unsigned long long r;
    unsigned int wi = __float_as_uint(w);
    asm("mov.b64 %0, {%1, %1};" : "=l"(r) : "r"(wi));
    return r;
}
__device__ __forceinline__ void fma2(unsigned long long& d, unsigned long long a,
                                     unsigned long long b) {
    asm("fma.rn.f32x2 %0, %1, %2, %0;" : "+l"(d) : "l"(a), "l"(b));
}
__device__ __forceinline__ unsigned long long mul2(unsigned long long a,
                                                   unsigned long long b) {
    unsigned long long d;
    asm("mul.rn.f32x2 %0, %1, %2;" : "=l"(d) : "l"(a), "l"(b));
    return d;
}

__global__ void __launch_bounds__(1024, 1)
honu_main(const float* __restrict__ x, const float* __restrict__ w,
          float* __restrict__ out) {
    extern __shared__ float smem[];
    float* xs   = smem;                   // [129][256] feature-major
    float* obuf = smem + NFEAT * NROW;    // [32][128] per-warp half-row partials
    __shared__ int sP4[130];              // prefix of c-steps before feature b
    __shared__ int is_last;

    int tid = threadIdx.x;

    // ---- prefix table ----
    if (tid < 130) {
        int p = 0;
        for (int bb = 0; bb < tid && bb < NFEAT; bb++)
            p += (bb / 4 + 1) * (NFEAT - bb);
        sP4[tid] = p;                     // sP4[129] == T4
    }

    // ---- x transposed into smem (4 thread-groups of 256 do 32 features) ----
    {
        int r = tid & 255, h = tid >> 8;  // h = 0..3
        const float4* xg = (const float4*)(x + (size_t)r * 128 + h * 32);
#pragma unroll
        for (int k = 0; k < 8; k++) {
            float4 v = xg[k];
            int f = h * 32 + 4 * k;
            xs[(f + 1) * NROW + r] = v.x;
            xs[(f + 2) * NROW + r] = v.y;
            xs[(f + 3) * NROW + r] = v.z;
            xs[(f + 4) * NROW + r] = v.w;
        }
        if (h == 0) xs[r] = 1.0f;         // bias feature
    }
    __syncthreads();

    int warp = tid >> 5, lane = tid & 31;
    int worker = blockIdx.x * WPB + warp;
    int range = worker >> 1;
    int rh    = worker & 1;               // 0 -> rows 0-127, 1 -> rows 128-255

    int s = (int)(((long long)T4 * range) / NRANGE);
    int e = (int)(((long long)T4 * (range + 1)) / NRANGE);

    // ---- decode start -> (b, quartet o, c-offset) via binary search ----
    int lo = 0, hi = NFEAT - 1;
    while (lo < hi) {                     // largest b with sP4[b] <= s
        int mid = (lo + hi + 1) >> 1;
        if (sP4[mid] <= s) lo = mid; else hi = mid - 1;
    }
    int b = lo;
    int rem = s - sP4[b];
    int L = NFEAT - b;
    int o = rem / L;
    int coff = rem % L;
    int pos = s;

    unsigned long long ov0 = 0, ov1 = 0;  // 4 rows as 2x f32x2

    const ulonglong2* xs2 = (const ulonglong2*)xs;  // 64 16B-quads per feature
    const int lq = rh * 32 + lane;        // this thread's quad within a feature

    while (pos < e) {
        L = NFEAT - b;
        int a0 = o << 2;
        int na = b + 1 - a0;
        if (na > 4) na = 4;
        int seg = L - coff;
        if (seg > e - pos) seg = e - pos;

        int woff[4];                      // 32-bit offsets into w
#pragma unroll
        for (int j = 0; j < 4; j++) {
            int aj = (j < na) ? (a0 + j) : a0;   // dead streams alias stream 0
            woff[j] = comb_base(aj, b) + coff;
        }

        unsigned long long acc[4][2];
#pragma unroll
        for (int j = 0; j < 4; j++) { acc[j][0] = 0; acc[j][1] = 0; }

        const ulonglong2* xp = xs2 + (size_t)(b + coff) * 64 + lq;

        int q = 0;
        for (; q + 2 <= seg; q += 2) {
            float wa[4], wb[4];           // front-loaded: 8 LDGs in flight
#pragma unroll
            for (int j = 0; j < 4; j++) {
                wa[j] = __ldg(w + woff[j] + q);
                wb[j] = __ldg(w + woff[j] + q + 1);
            }
            ulonglong2 x0 = xp[0];        // this half's quad, feature b+coff+q
#pragma unroll
            for (int j = 0; j < 4; j++) {
                unsigned long long w2 = pack2(wa[j]);
                fma2(acc[j][0], w2, x0.x);
                fma2(acc[j][1], w2, x0.y);
            }
            ulonglong2 x1 = xp[64];       // feature +1
#pragma unroll
            for (int j = 0; j < 4; j++) {
                unsigned long long w2 = pack2(wb[j]);
                fma2(acc[j][0], w2, x1.x);
                fma2(acc[j][1], w2, x1.y);
            }
            xp += 128;
        }
        if (q < seg) {                    // odd tail step
            ulonglong2 x0 = xp[0];
#pragma unroll
            for (int j = 0; j < 4; j++) {
                unsigned long long w2 = pack2(__ldg(w + woff[j] + q));
                fma2(acc[j][0], w2, x0.x);
                fma2(acc[j][1], w2, x0.y);
            }
        }

        // epilogue: out += (x_a * x_b) * s_ab  (linearity allows partial runs)
        {
            ulonglong2 xb = xs2[(size_t)b * 64 + lq];
#pragma unroll
            for (int j = 0; j < 4; j++) {
                if (j < na) {
                    ulonglong2 xa = xs2[(size_t)(a0 + j) * 64 + lq];
                    fma2(ov0, mul2(xa.x, xb.x), acc[j][0]);
                    fma2(ov1, mul2(xa.y, xb.y), acc[j][1]);
                }
            }
        }

        pos += seg;
        coff += seg;
        if (coff == L) {
            coff = 0;
            o++;
            if ((o << 2) > b) { o = 0; b++; }
        }
    }

    // ---- per-warp half-row partials -> smem, block combine -> global ----
    {
        float4* ob = (float4*)(obuf + warp * 128);
        union { unsigned long long q[2]; float4 f; } u;
        u.q[0] = ov0; u.q[1] = ov1;
        ob[lane] = u.f;                   // rows rh*128 + 4*lane .. +3
    }
    __syncthreads();
    if (tid < NROW) {
        int trh = tid >> 7, rr = tid & 127;
        float ssum = 0.0f;
#pragma unroll
        for (int k = 0; k < WPB / 2; k++) ssum += obuf[(2 * k + trh) * 128 + rr];
        g_partial[blockIdx.x * NROW + tid] = ssum;
    }

    // ---- fused cross-block reduction: last block reduces ----
    __threadfence();
    __syncthreads();
    if (tid == 0) is_last = (atomicAdd(&g_count, 1) == NBLK - 1);
    __syncthreads();
    if (is_last && tid < NROW) {
        __threadfence();
        float s0 = 0.f, s1 = 0.f, s2 = 0.f, s3 = 0.f;
#pragma unroll
        for (int i = 0; i < NBLK; i += 4) {
            s0 += g_partial[(i + 0) * NROW + tid];
            s1 += g_partial[(i + 1) * NROW + tid];
            s2 += g_partial[(i + 2) * NROW + tid];
            s3 += g_partial[(i + 3) * NROW + tid];
        }
        out[tid] = (s0 + s1) + (s2 + s3);
        if (tid == 0) g_count = 0;        // reset for next graph replay
    }
}

extern "C" void kernel_launch(void* const* d_in, const int* in_sizes, int n_in,
                              void* d_out, int out_size) {
    (void)in_sizes; (void)n_in; (void)out_size;
    const float* x = (const float*)d_in[0];
    const float* w = (const float*)d_in[1];
    // d_in[2] (comb_idx) intentionally unused: lexicographic rank is closed-form.

    size_t smem_bytes = (size_t)(NFEAT * NROW + WPB * 128) * sizeof(float);  // 148,480 B
    cudaFuncSetAttribute(honu_main, cudaFuncAttributeMaxDynamicSharedMemorySize,
                         (int)smem_bytes);
    honu_main<<<NBLK, 1024, smem_bytes>>>(x, w, (float*)d_out);
}